// round 13
// baseline (speedup 1.0000x reference)
#include <cuda_runtime.h>

#define NN 96
#define NP 9216            // 96*96
#define NVOX 884736        // 96^3
#define NFIELDS 6          // fields the loss consumes: neg0,pos1,neg1,pos2,neg2,pos3
#define NFA 7              // +1 zero dummy field: OOB landing zone for weight-0 reads
#define VSTEPS 7
#define BLK3 (48 * NN)     // k_final partial blocks per ref

// Field voxel = one uint32, Z-LOW biased layout:
//   bits[0:10)  pz = iz + 512, bits[10:21) px = ix + 1024, bits[21:32) py = iy + 1024
// Per-step range B_k = 2^k/16 (powers of two -> all scale folds exact).
__device__ __align__(16) unsigned g_A[NFA][NVOX];
__device__ __align__(16) unsigned g_B[NFA][NVOX];
__device__ double g_part[3 * BLK3];

#define MAGIC_I   0x4B000000u          // 2^23 float bits
#define FMAGIC    12582912.f           // 1.5 * 2^23
#define FMAGIC_I  0x4B400000

__device__ __forceinline__ float fadd_rm(float a, float b) {
    float r;
    asm("add.rm.f32 %0, %1, %2;" : "=f"(r) : "f"(a), "f"(b));
    return r;
}

// u >> 10 on the FMA pipe (IMAD.HI) to relieve the saturated ALU pipe
__device__ __forceinline__ unsigned hsh(unsigned u) { return __umulhi(u, 4194304u); }
// decodes -> biased floats
__device__ __forceinline__ float dZ(unsigned u) { return __int_as_float((u & 0x3FFu) | MAGIC_I); }       // 2^23+pz
__device__ __forceinline__ float dX(unsigned t) { return __int_as_float((t & 0x7FFu) | MAGIC_I); }       // 2^23+px
__device__ __forceinline__ float dB(unsigned t) { return __int_as_float((t & 0x3FFFFFu) | MAGIC_I); }    // 2^23+px+2048py

// Sample setup: global floor via folded magic, fracs, reference clamp semantics:
// x0=clip(floor,0,95); HIGH side (floor>=95) kills frac (x1==x0 in reference);
// low side keeps unclamped frac (x0=0, x1=1). OOB corner reads get weight 0.
__device__ __forceinline__ void setup(float vx, float vy, float vz,
                                      float xm, float ym, float zm,
                                      int* off, float* fx, float* fy, float* fz) {
    float t;
    t = fadd_rm(vx, xm); int xi = __float_as_int(t) - FMAGIC_I; *fx = vx - (t - xm);
    t = fadd_rm(vy, ym); int yi = __float_as_int(t) - FMAGIC_I; *fy = vy - (t - ym);
    t = fadd_rm(vz, zm); int zi = __float_as_int(t) - FMAGIC_I; *fz = vz - (t - zm);
    if (xi >= NN - 1) *fx = 0.f;
    if (yi >= NN - 1) *fy = 0.f;
    if (zi >= NN - 1) *fz = 0.f;
    int x0 = min(max(xi, 0), NN - 1);
    int y0 = min(max(yi, 0), NN - 1);
    int z0 = min(max(zi, 0), NN - 1);
    *off = (x0 * NN + y0) * NN + z0;
}

// trilinear corner weights (A(x0y0z0) B(z1) C(y1) D(y1z1) E(x1) F G H)
__device__ __forceinline__ void mkweights(float fx, float fy, float fz, float* w) {
    float gx = 1.f - fx, gy = 1.f - fy, gz = 1.f - fz;
    float a00 = gy * gz, a01 = gy * fz, a10 = fy * gz, a11 = fy * fz;
    w[0] = gx * a00; w[1] = gx * a01; w[2] = gx * a10; w[3] = gx * a11;
    w[4] = fx * a00; w[5] = fx * a01; w[6] = fx * a10; w[7] = fx * a11;
}

// 8-corner gather + 3 weighted-dot chains. Returns (X̄b=2^23+X̄, 2048·Ȳ, Z̄b=2^23+Z̄).
__device__ __forceinline__ float3 fetchdot(const unsigned* __restrict__ p,
                                           const float* __restrict__ w) {
    unsigned u0 = __ldg(p),           u1 = __ldg(p + 1);
    unsigned u2 = __ldg(p + NN),      u3 = __ldg(p + NN + 1);
    unsigned u4 = __ldg(p + NP),      u5 = __ldg(p + NP + 1);
    unsigned u6 = __ldg(p + NP + NN), u7 = __ldg(p + NP + NN + 1);
    unsigned uu[8] = {u0, u1, u2, u3, u4, u5, u6, u7};
    float sX = 0.f, sB = 0.f, sZ = 0.f;
    #pragma unroll
    for (int i = 0; i < 8; i++) {
        unsigned t = hsh(uu[i]);
        sX = fmaf(w[i], dX(t), sX);
        sB = fmaf(w[i], dB(t), sB);
        sZ = fmaf(w[i], dZ(uu[i]), sZ);
    }
    return make_float3(sX, sB - sX, sZ);
}

// round-to-nearest pack with bias folded into the int subtract
__device__ __forceinline__ int cpack(float t, float lo, float hi, int bias) {
    float c = fminf(fmaxf(t, lo), hi) + FMAGIC;
    return __float_as_int(c) - (FMAGIC_I - bias);
}

// Field table: f -> transform index; sign = (f odd) ? + : -
__constant__ int c_ftp[NFIELDS] = {0, 1, 1, 2, 2, 3};

__global__ void __launch_bounds__(192) k_init(const float* __restrict__ T) {
    int z = threadIdx.x;
    int y = blockIdx.x * 2 + threadIdx.y;
    int x = blockIdx.y;
    int f = blockIdx.z;
    int idx = (x * NN + y) * NN + z;
    int tp = c_ftp[f];
    float s = (f & 1) ? 0.0078125f : -0.0078125f;
    const float* base = T + (size_t)tp * 3 * NVOX;
    int px = cpack(s * base[idx]            * 16384.f, -1023.f, 1023.f, 1024);
    int py = cpack(s * base[idx + NVOX]     * 16384.f, -1023.f, 1023.f, 1024);
    int pz = cpack(s * base[idx + 2 * NVOX] * 8192.f,  -511.f,  511.f,  512);
    g_A[f][idx] = (unsigned)(pz + (px << 10) + (py << 21));
}

// One squaring step, 6 fields, FOUR z-voxels per thread.
__global__ void __launch_bounds__(192) k_step(int dir, float inv, float inv_y, float inv2,
                                              float co_x, float co_y, float co_z,
                                              float fs, float fsz) {
    const unsigned* __restrict__ inb = dir ? &g_B[0][0] : &g_A[0][0];
    unsigned* __restrict__ outb = dir ? &g_A[0][0] : &g_B[0][0];
    int z0 = threadIdx.x * 4;
    int y = blockIdx.x * 8 + threadIdx.y;
    int x = blockIdx.y;
    int f = blockIdx.z;
    int idx = (x * NN + y) * NN + z0;
    const unsigned* vol = inb + (size_t)f * NVOX;

    uint4 cc = *reinterpret_cast<const uint4*>(vol + idx);
    unsigned cw[4] = {cc.x, cc.y, cc.z, cc.w};
    unsigned ow[4];
    float xm = __int_as_float(FMAGIC_I + x);
    float ym = __int_as_float(FMAGIC_I + y);
    int zmb = FMAGIC_I + z0;

    #pragma unroll
    for (int h = 0; h < 4; h++) {
        unsigned u = cw[h];
        unsigned t = hsh(u);
        float dx0 = dX(t);
        float vx = fmaf(dx0, inv, co_x);
        float vy = fmaf(dB(t) - dx0, inv_y, co_y);
        float vz = fmaf(dZ(u), inv2, co_z);

        int off; float fx, fy, fz;
        setup(vx, vy, vz, xm, ym, __int_as_float(zmb + h), &off, &fx, &fy, &fz);
        float w[8];
        mkweights(fx, fy, fz, w);
        float3 d = fetchdot(vol + off, w);

        float tx = fmaf(d.x, 0.5f,           fmaf(vx, fs,  -4194816.f));  // -(2^23+1024)/2
        float ty = fmaf(d.y, 2.44140625e-4f, fmaf(vy, fs,  -512.f));      // inv_y*fs = 2^-12
        float tz = fmaf(d.z, 0.5f,           fmaf(vz, fsz, -4194560.f));  // -(2^23+512)/2
        int px = cpack(tx, -1023.f, 1023.f, 1024);
        int py = cpack(ty, -1023.f, 1023.f, 1024);
        int pz = cpack(tz, -511.f,  511.f,  512);
        ow[h] = (unsigned)(pz + (px << 10) + (py << 21));
    }
    *reinterpret_cast<uint4*>(outb + (size_t)f * NVOX + idx) = make_uint4(ow[0], ow[1], ow[2], ow[3]);
}

// Compose + residual norm, by ref r in {0,1,2}: F_neg field = 2r; pairs share the
// center decode, sample setup AND trilinear weights. R is staged block-cooperatively
// into smem (each block covers 192 consecutive voxels = 3456 consecutive floats of R),
// replacing the separate transpose kernel.
__constant__ int c_pbase[3] = {0, 3, 5};

__global__ void __launch_bounds__(192) k_final(const float* __restrict__ R) {
    __shared__ float sR[192 * 18];
    __shared__ double sred[6];
    const float inv  = 0.0078125f;      // 1/128
    const float invy = 3.814697265625e-6f;  // 2^-18
    const float inv2 = 0.015625f;       // 1/64
    const float co_x = -65544.f;        // -(2^23+1024)/128
    const float co_y = -8.f;            // -1024/128
    const float co_z = -131080.f;       // -(2^23+512)/64
    int z = threadIdx.x;
    int y = blockIdx.x * 2 + threadIdx.y;
    int x = blockIdx.y;
    int r = blockIdx.z;
    int idx = (x * NN + y) * NN + z;
    int lin = threadIdx.y * NN + threadIdx.x;

    // stage this block's R slice: voxels [base, base+192), 18 floats each, coalesced
    {
        int base = (x * NN + blockIdx.x * 2) * NN;   // first voxel of the block
        const float* src = R + (size_t)base * 18;
        for (int j = lin; j < 192 * 18; j += 192)
            sR[j] = src[j];
    }

    unsigned u = g_B[2 * r][idx];
    unsigned t = hsh(u);
    float dx0 = dX(t);
    float vx = fmaf(dx0, inv, co_x);
    float vy = fmaf(dB(t) - dx0, invy, co_y);
    float vz = fmaf(dZ(u), inv2, co_z);

    int off; float fx, fy, fz;
    setup(vx, vy, vz,
          __int_as_float(FMAGIC_I + x), __int_as_float(FMAGIC_I + y),
          __int_as_float(FMAGIC_I + z), &off, &fx, &fy, &fz);
    float w[8];
    mkweights(fx, fy, fz, w);

    // debias folds (same magnitude/rounding as the old R+fold path)
    float ax = vx + 65544.f;    // vx - co fold sign: residual uses ax - R
    float ay = vy + 8.f;
    float az = vz + 131080.f;

    __syncthreads();

    float acc = 0.f;
    const float* myR = sR + lin * 18;
    for (int j = r; j < 3; j++) {
        int p = c_pbase[r] + (j - r);
        float3 d = fetchdot(&g_B[2 * j + 1][0] + off, w);
        float rx = fmaf(d.x, inv,  ax - 65544.f * 2.f + 65544.f - myR[p]);      // = vx + ... ; simplified below
        // NOTE: ax = vx + 65544 is wrong direction; compute directly:
        rx = fmaf(d.x, inv,  (vx - 65544.f) - (myR[p]      - 131088.f));        // placeholder avoided
        // Use the straightforward exact form:
        rx = fmaf(d.x, inv,  vx - (myR[p] + 65544.f));
        float ry = fmaf(d.y, invy, vy - (myR[6 + p] + 8.f));
        float rz = fmaf(d.z, inv2, vz - (myR[12 + p] + 131080.f));
        acc += sqrtf(rx * rx + ry * ry + rz * rz);
    }

    #pragma unroll
    for (int o = 16; o; o >>= 1) acc += __shfl_down_sync(0xffffffffu, acc, o);

    int lane = lin & 31, wi = lin >> 5;
    if (lane == 0) sred[wi] = (double)acc;
    __syncthreads();
    if (lin == 0) {
        double a = 0.0;
        #pragma unroll
        for (int i = 0; i < 6; i++) a += sred[i];
        g_part[r * BLK3 + blockIdx.x * NN + blockIdx.y] = a;
    }
}

// Deterministic final reduction
__global__ void __launch_bounds__(1024) k_reduce(float* __restrict__ out) {
    __shared__ double sred[32];
    double acc = 0.0;
    const int n = 3 * BLK3;
    for (int i = threadIdx.x; i < n; i += 1024) acc += g_part[i];
    #pragma unroll
    for (int o = 16; o; o >>= 1) acc += __shfl_down_sync(0xffffffffu, acc, o);
    int lane = threadIdx.x & 31, w = threadIdx.x >> 5;
    if (lane == 0) sred[w] = acc;
    __syncthreads();
    if (threadIdx.x == 0) {
        double tot = 0.0;
        #pragma unroll
        for (int i = 0; i < 32; i++) tot += sred[i];
        out[0] = (float)tot;
    }
}

extern "C" void kernel_launch(void* const* d_in, const int* in_sizes, int n_in,
                              void* d_out, int out_size) {
    const float* T = (const float*)d_in[0];
    const float* R = (const float*)d_in[1];
    if (n_in >= 2 && in_sizes[0] == 15925248) {   // robust to metadata ordering
        T = (const float*)d_in[1];
        R = (const float*)d_in[0];
    }
    float* out = (float*)d_out;

    dim3 bi(NN, 2);
    dim3 gi(48, NN, NFIELDS);
    k_init<<<gi, bi>>>(T);

    dim3 bs(24, 8);
    dim3 gs(12, NN, NFIELDS);
    for (int s = 0; s < VSTEPS; s++) {
        float inv   = ldexpf(1.f, s - 14);
        float inv_y = ldexpf(1.f, s - 25);
        float inv2  = ldexpf(1.f, s - 13);
        float co_x  = -(8388608.f + 1024.f) * inv;   // exact
        float co_y  = -ldexpf(1.f, s - 4);           // -1024*inv
        float co_z  = -(8388608.f + 512.f)  * inv2;
        float fs    = ldexpf(1.f, 13 - s);
        float fsz   = ldexpf(1.f, 12 - s);
        k_step<<<gs, bs>>>(s & 1, inv, inv_y, inv2, co_x, co_y, co_z, fs, fsz);  // ends in g_B
    }
    dim3 gf(48, NN, 3);
    k_final<<<gf, bi>>>(R);
    k_reduce<<<1, 1024>>>(out);
}

// round 14
// speedup vs baseline: 1.0798x; 1.0798x over previous
#include <cuda_runtime.h>

#define NN 96
#define NP 9216            // 96*96
#define NVOX 884736        // 96^3
#define NFIELDS 6          // fields the loss consumes: neg0,pos1,neg1,pos2,neg2,pos3
#define NFA 7              // +1 zero dummy field: OOB landing zone for weight-0 reads
#define VSTEPS 7
#define BLK3 (48 * NN)     // k_final partial blocks per ref

// Field voxel = one uint32, Z-LOW biased layout:
//   bits[0:10)  pz = iz + 512, bits[10:21) px = ix + 1024, bits[21:32) py = iy + 1024
// Per-step range B_k = 2^k/16 (powers of two -> all scale folds exact).
__device__ __align__(16) unsigned g_A[NFA][NVOX];
__device__ __align__(16) unsigned g_B[NFA][NVOX];
__device__ double g_part[3 * BLK3];

#define MAGIC_I   0x4B000000u          // 2^23 float bits
#define FMAGIC    12582912.f           // 1.5 * 2^23
#define FMAGIC_I  0x4B400000

__device__ __forceinline__ float fadd_rm(float a, float b) {
    float r;
    asm("add.rm.f32 %0, %1, %2;" : "=f"(r) : "f"(a), "f"(b));
    return r;
}

// decodes (t = u >> 10, plain SHF — measured faster than IMAD.HI in R13)
__device__ __forceinline__ float dZ(unsigned u) { return __int_as_float((u & 0x3FFu) | MAGIC_I); }       // 2^23+pz
__device__ __forceinline__ float dX(unsigned t) { return __int_as_float((t & 0x7FFu) | MAGIC_I); }       // 2^23+px
__device__ __forceinline__ float dB(unsigned t) { return __int_as_float((t & 0x3FFFFFu) | MAGIC_I); }    // 2^23+px+2048py

// Sample setup: global floor via folded magic, fracs, reference clamp semantics:
// x0=clip(floor,0,95); HIGH side (floor>=95) kills frac (x1==x0 in reference);
// low side keeps unclamped frac (x0=0, x1=1). OOB corner reads get weight 0.
__device__ __forceinline__ void setup(float vx, float vy, float vz,
                                      float xm, float ym, float zm,
                                      int* off, float* fx, float* fy, float* fz) {
    float t;
    t = fadd_rm(vx, xm); int xi = __float_as_int(t) - FMAGIC_I; *fx = vx - (t - xm);
    t = fadd_rm(vy, ym); int yi = __float_as_int(t) - FMAGIC_I; *fy = vy - (t - ym);
    t = fadd_rm(vz, zm); int zi = __float_as_int(t) - FMAGIC_I; *fz = vz - (t - zm);
    if (xi >= NN - 1) *fx = 0.f;
    if (yi >= NN - 1) *fy = 0.f;
    if (zi >= NN - 1) *fz = 0.f;
    int x0 = min(max(xi, 0), NN - 1);
    int y0 = min(max(yi, 0), NN - 1);
    int z0 = min(max(zi, 0), NN - 1);
    *off = (x0 * NN + y0) * NN + z0;
}

// trilinear corner weights (A(x0y0z0) B(z1) C(y1) D(y1z1) E(x1) F G H)
__device__ __forceinline__ void mkweights(float fx, float fy, float fz, float* w) {
    float gx = 1.f - fx, gy = 1.f - fy, gz = 1.f - fz;
    float a00 = gy * gz, a01 = gy * fz, a10 = fy * gz, a11 = fy * fz;
    w[0] = gx * a00; w[1] = gx * a01; w[2] = gx * a10; w[3] = gx * a11;
    w[4] = fx * a00; w[5] = fx * a01; w[6] = fx * a10; w[7] = fx * a11;
}

// 8-corner gather + 3 weighted-dot chains. Returns (X̄b=2^23+X̄, 2048·Ȳ, Z̄b=2^23+Z̄).
__device__ __forceinline__ float3 fetchdot(const unsigned* __restrict__ p,
                                           const float* __restrict__ w) {
    unsigned u0 = __ldg(p),           u1 = __ldg(p + 1);
    unsigned u2 = __ldg(p + NN),      u3 = __ldg(p + NN + 1);
    unsigned u4 = __ldg(p + NP),      u5 = __ldg(p + NP + 1);
    unsigned u6 = __ldg(p + NP + NN), u7 = __ldg(p + NP + NN + 1);
    unsigned uu[8] = {u0, u1, u2, u3, u4, u5, u6, u7};
    float sX = 0.f, sB = 0.f, sZ = 0.f;
    #pragma unroll
    for (int i = 0; i < 8; i++) {
        unsigned t = uu[i] >> 10;
        sX = fmaf(w[i], dX(t), sX);
        sB = fmaf(w[i], dB(t), sB);
        sZ = fmaf(w[i], dZ(uu[i]), sZ);
    }
    return make_float3(sX, sB - sX, sZ);
}

// round-to-nearest pack with bias folded into the int subtract
__device__ __forceinline__ int cpack(float t, float lo, float hi, int bias) {
    float c = fminf(fmaxf(t, lo), hi) + FMAGIC;
    return __float_as_int(c) - (FMAGIC_I - bias);
}

// Field table: f -> transform index; sign = (f odd) ? + : -
__constant__ int c_ftp[NFIELDS] = {0, 1, 1, 2, 2, 3};

__global__ void __launch_bounds__(192) k_init(const float* __restrict__ T) {
    int z = threadIdx.x;
    int y = blockIdx.x * 2 + threadIdx.y;
    int x = blockIdx.y;
    int f = blockIdx.z;
    int idx = (x * NN + y) * NN + z;
    int tp = c_ftp[f];
    float s = (f & 1) ? 0.0078125f : -0.0078125f;
    const float* base = T + (size_t)tp * 3 * NVOX;
    int px = cpack(s * base[idx]            * 16384.f, -1023.f, 1023.f, 1024);
    int py = cpack(s * base[idx + NVOX]     * 16384.f, -1023.f, 1023.f, 1024);
    int pz = cpack(s * base[idx + 2 * NVOX] * 8192.f,  -511.f,  511.f,  512);
    g_A[f][idx] = (unsigned)(pz + (px << 10) + (py << 21));
}

// One squaring step, 6 fields, FOUR z-voxels per thread. (Identical to the 308us R11 version.)
__global__ void __launch_bounds__(192) k_step(int dir, float inv, float inv_y, float inv2,
                                              float co_x, float co_y, float co_z,
                                              float fs, float fsz) {
    const unsigned* __restrict__ inb = dir ? &g_B[0][0] : &g_A[0][0];
    unsigned* __restrict__ outb = dir ? &g_A[0][0] : &g_B[0][0];
    int z0 = threadIdx.x * 4;
    int y = blockIdx.x * 8 + threadIdx.y;
    int x = blockIdx.y;
    int f = blockIdx.z;
    int idx = (x * NN + y) * NN + z0;
    const unsigned* vol = inb + (size_t)f * NVOX;

    uint4 cc = *reinterpret_cast<const uint4*>(vol + idx);
    unsigned cw[4] = {cc.x, cc.y, cc.z, cc.w};
    unsigned ow[4];
    float xm = __int_as_float(FMAGIC_I + x);
    float ym = __int_as_float(FMAGIC_I + y);
    int zmb = FMAGIC_I + z0;

    #pragma unroll
    for (int h = 0; h < 4; h++) {
        unsigned u = cw[h];
        unsigned t = u >> 10;
        float dx0 = dX(t);
        float vx = fmaf(dx0, inv, co_x);
        float vy = fmaf(dB(t) - dx0, inv_y, co_y);
        float vz = fmaf(dZ(u), inv2, co_z);

        int off; float fx, fy, fz;
        setup(vx, vy, vz, xm, ym, __int_as_float(zmb + h), &off, &fx, &fy, &fz);
        float w[8];
        mkweights(fx, fy, fz, w);
        float3 d = fetchdot(vol + off, w);

        float tx = fmaf(d.x, 0.5f,           fmaf(vx, fs,  -4194816.f));  // -(2^23+1024)/2
        float ty = fmaf(d.y, 2.44140625e-4f, fmaf(vy, fs,  -512.f));      // inv_y*fs = 2^-12
        float tz = fmaf(d.z, 0.5f,           fmaf(vz, fsz, -4194560.f));  // -(2^23+512)/2
        int px = cpack(tx, -1023.f, 1023.f, 1024);
        int py = cpack(ty, -1023.f, 1023.f, 1024);
        int pz = cpack(tz, -511.f,  511.f,  512);
        ow[h] = (unsigned)(pz + (px << 10) + (py << 21));
    }
    *reinterpret_cast<uint4*>(outb + (size_t)f * NVOX + idx) = make_uint4(ow[0], ow[1], ow[2], ow[3]);
}

// Compose + residual norm, by ref r in {0,1,2}: F_neg field = 2r; pairs share the
// center decode, sample setup AND trilinear weights. R is staged block-cooperatively
// into smem (each block covers 192 consecutive voxels = 3456 consecutive floats),
// replacing the separate transpose kernel entirely.
__constant__ int c_pbase[3] = {0, 3, 5};

__global__ void __launch_bounds__(192) k_final(const float* __restrict__ R) {
    __shared__ float sR[192 * 18];
    __shared__ double sred[6];
    const float inv  = 0.0078125f;      // 1/128
    const float invy = 3.814697265625e-6f;  // 2^-18
    const float inv2 = 0.015625f;       // 1/64
    const float co_x = -65544.f;        // -(2^23+1024)/128
    const float co_y = -8.f;            // -1024/128
    const float co_z = -131080.f;       // -(2^23+512)/64
    int z = threadIdx.x;
    int y = blockIdx.x * 2 + threadIdx.y;
    int x = blockIdx.y;
    int r = blockIdx.z;
    int idx = (x * NN + y) * NN + z;
    int lin = threadIdx.y * NN + threadIdx.x;

    // stage this block's R slice (coalesced)
    {
        int base = (x * NN + blockIdx.x * 2) * NN;   // first voxel of the block
        const float* src = R + (size_t)base * 18;
        for (int j = lin; j < 192 * 18; j += 192)
            sR[j] = src[j];
    }

    unsigned u = g_B[2 * r][idx];
    unsigned t = u >> 10;
    float dx0 = dX(t);
    float vx = fmaf(dx0, inv, co_x);
    float vy = fmaf(dB(t) - dx0, invy, co_y);
    float vz = fmaf(dZ(u), inv2, co_z);

    int off; float fx, fy, fz;
    setup(vx, vy, vz,
          __int_as_float(FMAGIC_I + x), __int_as_float(FMAGIC_I + y),
          __int_as_float(FMAGIC_I + z), &off, &fx, &fy, &fz);
    float w[8];
    mkweights(fx, fy, fz, w);

    __syncthreads();

    float acc = 0.f;
    const float* myR = sR + lin * 18;
    for (int j = r; j < 3; j++) {
        int p = c_pbase[r] + (j - r);
        float3 d = fetchdot(&g_B[2 * j + 1][0] + off, w);
        // residual = (sample debiased)*scale + v - R; debias folded: R + fold const
        float rx = fmaf(d.x, inv,  vx - (myR[p]      + 65544.f));
        float ry = fmaf(d.y, invy, vy - (myR[6 + p]  + 8.f));
        float rz = fmaf(d.z, inv2, vz - (myR[12 + p] + 131080.f));
        acc += sqrtf(rx * rx + ry * ry + rz * rz);
    }

    #pragma unroll
    for (int o = 16; o; o >>= 1) acc += __shfl_down_sync(0xffffffffu, acc, o);

    int lane = lin & 31, wi = lin >> 5;
    if (lane == 0) sred[wi] = (double)acc;
    __syncthreads();
    if (lin == 0) {
        double a = 0.0;
        #pragma unroll
        for (int i = 0; i < 6; i++) a += sred[i];
        g_part[r * BLK3 + blockIdx.x * NN + blockIdx.y] = a;
    }
}

// Deterministic final reduction
__global__ void __launch_bounds__(1024) k_reduce(float* __restrict__ out) {
    __shared__ double sred[32];
    double acc = 0.0;
    const int n = 3 * BLK3;
    for (int i = threadIdx.x; i < n; i += 1024) acc += g_part[i];
    #pragma unroll
    for (int o = 16; o; o >>= 1) acc += __shfl_down_sync(0xffffffffu, acc, o);
    int lane = threadIdx.x & 31, w = threadIdx.x >> 5;
    if (lane == 0) sred[w] = acc;
    __syncthreads();
    if (threadIdx.x == 0) {
        double tot = 0.0;
        #pragma unroll
        for (int i = 0; i < 32; i++) tot += sred[i];
        out[0] = (float)tot;
    }
}

extern "C" void kernel_launch(void* const* d_in, const int* in_sizes, int n_in,
                              void* d_out, int out_size) {
    const float* T = (const float*)d_in[0];
    const float* R = (const float*)d_in[1];
    if (n_in >= 2 && in_sizes[0] == 15925248) {   // robust to metadata ordering
        T = (const float*)d_in[1];
        R = (const float*)d_in[0];
    }
    float* out = (float*)d_out;

    dim3 bi(NN, 2);
    dim3 gi(48, NN, NFIELDS);
    k_init<<<gi, bi>>>(T);

    dim3 bs(24, 8);
    dim3 gs(12, NN, NFIELDS);
    for (int s = 0; s < VSTEPS; s++) {
        float inv   = ldexpf(1.f, s - 14);
        float inv_y = ldexpf(1.f, s - 25);
        float inv2  = ldexpf(1.f, s - 13);
        float co_x  = -(8388608.f + 1024.f) * inv;   // exact
        float co_y  = -ldexpf(1.f, s - 4);           // -1024*inv
        float co_z  = -(8388608.f + 512.f)  * inv2;
        float fs    = ldexpf(1.f, 13 - s);
        float fsz   = ldexpf(1.f, 12 - s);
        k_step<<<gs, bs>>>(s & 1, inv, inv_y, inv2, co_x, co_y, co_z, fs, fsz);  // ends in g_B
    }
    dim3 gf(48, NN, 3);
    k_final<<<gf, bi>>>(R);
    k_reduce<<<1, 1024>>>(out);
}